// round 7
// baseline (speedup 1.0000x reference)
#include <cuda_runtime.h>
#include <cstdint>

namespace {

constexpr unsigned FULL = 0xffffffffu;

// ---------------------------------------------------------------------------
// GF(2) 8x8 matrix algebra (constexpr) — validated rounds 4-6.
// X basis: RX -> RZ, CNOT ring -> linear map P.
// <Z7> = (1/256) sum_v cos( sum_{active g} theta_g * (-1)^{par(a_g & v)} ).
// Embed gates collapse to qubits {0,4} (P^{-4} e7 = 0x11) => data phase is
// +-x0 +- x4; the 256-term sum factors through 4 weight-only coset sums.
// ---------------------------------------------------------------------------

struct M8 { uint8_t r[8]; };

__host__ __device__ constexpr M8 makeP() {
    M8 P{};
    for (int q = 0; q < 7; ++q) P.r[q] = uint8_t((1u << q) | (1u << (q + 1)));
    P.r[7] = uint8_t((1u << 7) | 3u);
    return P;
}
__host__ __device__ constexpr M8 ident() {
    M8 I{};
    for (int q = 0; q < 8; ++q) I.r[q] = uint8_t(1u << q);
    return I;
}
__host__ __device__ constexpr M8 matmul(const M8& A, const M8& B) {
    M8 C{};
    for (int q = 0; q < 8; ++q) {
        uint8_t row = 0;
        for (int k = 0; k < 8; ++k)
            if ((A.r[q] >> k) & 1u) row ^= B.r[k];
        C.r[q] = row;
    }
    return C;
}
__host__ __device__ constexpr M8 inverse(const M8& A) {
    unsigned m[8] = {};
    for (int q = 0; q < 8; ++q) m[q] = (unsigned)A.r[q] | (1u << (8 + q));
    for (int col = 0; col < 8; ++col) {
        int piv = col;
        while (!((m[piv] >> col) & 1u)) ++piv;
        unsigned t = m[col]; m[col] = m[piv]; m[piv] = t;
        for (int r = 0; r < 8; ++r)
            if (r != col && ((m[r] >> col) & 1u)) m[r] ^= m[col];
    }
    M8 R{};
    for (int q = 0; q < 8; ++q) R.r[q] = uint8_t(m[q] >> 8);
    return R;
}
__host__ __device__ constexpr M8 Pinv_pow(int k) {
    M8 Pi = inverse(makeP());
    M8 R = ident();
    for (int i = 0; i < k; ++i) R = matmul(Pi, R);
    return R;
}

struct WGates { int n; uint8_t a[32]; uint8_t idx[32]; };
__host__ __device__ constexpr WGates makeWG() {
    WGates G{};
    for (int l = 0; l < 4; ++l) {
        M8 A = Pinv_pow(4 - l);
        for (int q = 0; q < 8; ++q)
            if ((A.r[q] >> 7) & 1u) {
                G.a[G.n] = A.r[q];
                G.idx[G.n] = uint8_t(l * 8 + q);
                ++G.n;
            }
    }
    return G;
}
struct XGates { int n; uint8_t a[8]; uint8_t q[8]; };
__host__ __device__ constexpr XGates makeXG() {
    XGates G{};
    M8 A = Pinv_pow(4);
    for (int q = 0; q < 8; ++q)
        if ((A.r[q] >> 7) & 1u) {
            G.a[G.n] = A.r[q];
            G.q[G.n] = uint8_t(q);
            ++G.n;
        }
    return G;
}

// Sign-word columns: bit g of COL[i] = bit i of gate mask a_g.
struct Cols { uint32_t c[8]; };
__host__ __device__ constexpr Cols makeCols() {
    Cols C{};
    WGates G = makeWG();
    for (int i = 0; i < 8; ++i)
        for (int g = 0; g < G.n; ++g)
            if ((G.a[g] >> i) & 1u) C.c[i] |= 1u << g;
    return C;
}

constexpr int kThreads = 1024;
constexpr int kPixPerBlock = 64;
constexpr int kBlocks = 8192 / kPixPerBlock;   // 128 blocks

__device__ __forceinline__ void cw_sincos(float S, float& sv, float& cv) {
    const float k = rintf(S * 0.15915494309189535f);
    float r = fmaf(k, -6.283185482025146484f, S);
    r = fmaf(k, 1.7484556000744885e-7f, r);
    __sincosf(r, &sv, &cv);
}

__global__ __launch_bounds__(kThreads)
void qconv_fused(const float* __restrict__ x, const float* __restrict__ w,
                 float* __restrict__ out) {
    constexpr WGates WG = makeWG();
    constexpr XGates XG = makeXG();
    constexpr Cols CL = makeCols();
    static_assert(XG.n == 2, "embed collapse assumption violated");
    constexpr int MA = XG.a[0];
    constexpr int MB = XG.a[1];

    __shared__ float s_w[128];
    __shared__ float s_part[32][4];
    __shared__ float s_tab[4][4];

    const int tid = threadIdx.x;
    const int lane = tid & 31;
    const int wid = tid >> 5;

    // Prefetch pixel inputs (tid < 64) to overlap DRAM with phase 1.
    float x0 = 0.f, x1 = 0.f;
    int base = 0;
    if (tid < kPixPerBlock) {
        const int pixel = blockIdx.x * kPixPerBlock + tid;
        const int b = pixel >> 12;
        const int i = (pixel >> 6) & 63;
        const int j = pixel & 63;
        constexpr int q0 = XG.q[0], q1 = XG.q[1];
        constexpr int c0 = q0 >> 2, d0i = (q0 >> 1) & 1, d0j = q0 & 1;
        constexpr int c1 = q1 >> 2, d1i = (q1 >> 1) & 1, d1j = q1 & 1;
        x0 = __ldg(&x[((b * 2 + c0) * 128 + (2 * i + d0i)) * 128 + (2 * j + d0j)]);
        x1 = __ldg(&x[((b * 2 + c1) * 128 + (2 * i + d1i)) * 128 + (2 * j + d1j)]);
        base = ((b * 4) * 64 + i) * 64 + j;
    }
    if (tid < 128) s_w[tid] = __ldg(&w[tid]);
    __syncthreads();

    // ---- Phase 1: one (channel, v) per thread; one sincos per thread. ----
    const int c = tid >> 8;      // 0..3
    const int v = tid & 255;     // full 8-bit v

    // All 26 gate signs at once: sw bit g = par(a_g & v).
    uint32_t sw = 0;
#pragma unroll
    for (int i = 0; i < 8; ++i)
        if ((v >> i) & 1) sw ^= CL.c[i];

    float S = 0.f;
#pragma unroll
    for (int g = 0; g < WG.n; ++g) {
        const float th = s_w[c * 32 + (int)WG.idx[g]];
        S += __int_as_float(__float_as_int(th) ^ (((sw >> g) & 1u) << 31));
    }

    float sv, cv;
    cw_sincos(S, sv, cv);

    const int pA = __popc(MA & v) & 1;
    const int pB = __popc(MB & v) & 1;
    const float sg = pA ? -sv : sv;
    const bool same = (pA == pB);
    float A = same ? cv : 0.f;
    float B = same ? sg : 0.f;
    float D = same ? 0.f : cv;
    float E = same ? 0.f : sg;

#pragma unroll
    for (int off = 16; off > 0; off >>= 1) {
        A += __shfl_xor_sync(FULL, A, off);
        B += __shfl_xor_sync(FULL, B, off);
        D += __shfl_xor_sync(FULL, D, off);
        E += __shfl_xor_sync(FULL, E, off);
    }
    if (lane == 0) {
        s_part[wid][0] = A; s_part[wid][1] = B;
        s_part[wid][2] = D; s_part[wid][3] = E;
    }
    __syncthreads();
    if (tid < 16) {
        const int cc = tid >> 2, comp = tid & 3;   // warps cc*8 .. cc*8+7
        float acc = 0.f;
#pragma unroll
        for (int k = 0; k < 8; ++k) acc += s_part[cc * 8 + k][comp];
        s_tab[cc][comp] = acc * (1.f / 256.f);
    }
    __syncthreads();

    // ---- Phase 2: one output pixel per thread (tid < 64). ----
    if (tid < kPixPerBlock) {
        float sp, cp, sm, cm;
        cw_sincos(x0 + x1, sp, cp);
        cw_sincos(x0 - x1, sm, cm);
#pragma unroll
        for (int oc = 0; oc < 4; ++oc) {
            const float r = fmaf(s_tab[oc][0], cp,
                            fmaf(-s_tab[oc][1], sp,
                            fmaf(s_tab[oc][2], cm, -s_tab[oc][3] * sm)));
            out[base + oc * 4096] = r;
        }
    }
}

}  // namespace

extern "C" void kernel_launch(void* const* d_in, const int* /*in_sizes*/, int /*n_in*/,
                              void* d_out, int /*out_size*/) {
    const float* x = (const float*)d_in[0];
    const float* w = (const float*)d_in[1];
    float* out = (float*)d_out;
    qconv_fused<<<kBlocks, kThreads>>>(x, w, out);
}